// round 16
// baseline (speedup 1.0000x reference)
#include <cuda_runtime.h>

#define DIM 64
#define MAX_NODES 100000
#define MAX_EDGES 1600000
#define CAP 64                       // fixed bucket capacity per node

typedef unsigned long long ull;

// ---- device scratch (no allocs allowed) ----
__device__ __align__(16) float g_h[MAX_NODES * DIM];      // h = x + aggr (written whole)
__device__ __align__(8) int2 g_edges[MAX_NODES * CAP];    // (src, edge_id) per dst bucket
__device__ int  g_cnt[MAX_NODES];
__device__ ull  g_wpack[8 * DIM];                         // (spacer use)
__device__ ull  g_bepack[32];                             // packed be pairs

__device__ __forceinline__ ull pk2(float lo, float hi) {
    ull r; asm("mov.b64 %0, {%1, %2};" : "=l"(r) : "f"(lo), "f"(hi)); return r;
}
__device__ __forceinline__ void upk2(float& lo, float& hi, ull v) {
    asm("mov.b64 {%0, %1}, %2;" : "=f"(lo), "=f"(hi) : "l"(v));
}
__device__ __forceinline__ void ffma2(ull& d, ull a, ull b) {
    asm("fma.rn.f32x2 %0, %1, %2, %0;" : "+l"(d) : "l"(a), "l"(b));
}
__device__ __forceinline__ unsigned smem_u32(const void* p) {
    unsigned a;
    asm("{ .reg .u64 t; cvta.to.shared.u64 t, %1; cvt.u32.u64 %0, t; }"
        : "=r"(a) : "l"(p));
    return a;
}
__device__ __forceinline__ void cpa16(unsigned s, const void* g) {
    asm volatile("cp.async.ca.shared.global [%0], [%1], 16;" :: "r"(s), "l"(g));
}
#define CP_COMMIT()  asm volatile("cp.async.commit_group;")
#define CP_WAIT(kk)  asm volatile("cp.async.wait_group " #kk ";")

__device__ __forceinline__ unsigned cvt_tf32(float f) {
    unsigned r;
    asm("cvt.rna.tf32.f32 %0, %1;" : "=r"(r) : "f"(f));
    return r;
}
// D = A(16x8) * B(8x8) + C, tf32 inputs, fp32 accum  (layouts verified in R14)
__device__ __forceinline__ void mma_tf32(float c[4], const unsigned a[4], const unsigned b[2]) {
    asm volatile(
        "mma.sync.aligned.m16n8k8.row.col.f32.tf32.tf32.f32 "
        "{%0,%1,%2,%3}, {%4,%5,%6,%7}, {%8,%9}, {%0,%1,%2,%3};"
        : "+f"(c[0]), "+f"(c[1]), "+f"(c[2]), "+f"(c[3])
        : "r"(a[0]), "r"(a[1]), "r"(a[2]), "r"(a[3]), "r"(b[0]), "r"(b[1]));
}

// ---------------------------------------------------------------------------
// k1 (spacer), k2 scatter, k3 pack be
// ---------------------------------------------------------------------------
__global__ void pack_we_kernel(const float* __restrict__ We) {
    const int f = blockIdx.x * blockDim.x + threadIdx.x;
    if (f < 8 * DIM) {
        const int k2 = f >> 6, j = f & 63;
        g_wpack[f] = pk2(We[(2 * k2) * DIM + j], We[(2 * k2 + 1) * DIM + j]);
    }
}

__global__ void scatter_kernel(const int* __restrict__ ei, int E) {
    int e = blockIdx.x * blockDim.x + threadIdx.x;
    if (e < E) {
        const int src = ei[e];
        const int dst = ei[E + e];
        const int p = atomicAdd(&g_cnt[dst], 1);
        if (p < CAP) g_edges[(size_t)dst * CAP + p] = make_int2(src, e);
    }
}

__global__ void pack_be_kernel(const float* __restrict__ be) {
    const int i = threadIdx.x;
    if (i < 32) g_bepack[i] = pk2(be[2 * i], be[2 * i + 1]);
}

// ---------------------------------------------------------------------------
// k4: aggregation = depth-4 node pipeline (R12) + tf32 MMA projection (R14
// fragments) + smem-bounced scalar epilogue (R12 layout).
// Per 16-edge sub-chunk: A frags from 80B-padded ea smem (conflict-free),
// 16 MMAs -> e tile stored to 68f-padded smem (conflict-free), epilogue:
// lane owns cols (2l,2l+1): 1 LDS.64 (e) + 1 coalesced LDG.64 (x) per edge.
// ---------------------------------------------------------------------------
#define EA_ROW_F 20                         // 80B padded ea rows
#define EB_ROW_F 17                         // 68B padded e rows (float2 granularity)
#define SB_STAGE_F (32 * EA_ROW_F)          // 640 floats / stage
#define AGG_SMEM_F (16 * SB_STAGE_F + 4 * (16 * EB_ROW_F * 4) /*see carve*/)

__device__ __forceinline__ void mma16_epi(
    const float* se,        // ea stage base (EA_ROW_F-float rows)
    float* eb,              // e-buffer for this warp (68-float rows: EB_ROW_F*4)
    const int* srcs,        // staged records (.x at 2*i)
    int s16, int mK,
    const float* __restrict__ x, int c0, int gID, int l4,
    const unsigned bf[8][2][2], float be0, float be1,
    float& acc0, float& acc1)
{
    // A fragments (both k-halves)
    unsigned af[2][4];
#pragma unroll
    for (int kk = 0; kk < 2; kk++) {
        const float* r0 = se + (s16 + gID) * EA_ROW_F + kk * 8;
        const float* r8 = se + (s16 + gID + 8) * EA_ROW_F + kk * 8;
        af[kk][0] = cvt_tf32(r0[l4]);
        af[kk][1] = cvt_tf32(r8[l4]);
        af[kk][2] = cvt_tf32(r0[l4 + 4]);
        af[kk][3] = cvt_tf32(r8[l4 + 4]);
    }
    float c[8][4];
#pragma unroll
    for (int t = 0; t < 8; t++) { c[t][0] = 0.f; c[t][1] = 0.f; c[t][2] = 0.f; c[t][3] = 0.f; }
#pragma unroll
    for (int kk = 0; kk < 2; kk++)
#pragma unroll
        for (int t = 0; t < 8; t++)
            mma_tf32(c[t], af[kk], bf[t][kk]);

    // store e tile to padded smem (row pitch 68 floats -> conflict-free)
#pragma unroll
    for (int t = 0; t < 8; t++) {
        *reinterpret_cast<float2*>(eb + gID * 68 + t * 8 + 2 * l4) =
            make_float2(c[t][0], c[t][1]);
        *reinterpret_cast<float2*>(eb + (gID + 8) * 68 + t * 8 + 2 * l4) =
            make_float2(c[t][2], c[t][3]);
    }
    __syncwarp();

    // scalar epilogue in R12 layout
    for (int j = 0; j < 16; j += 4) {
        float2 xv[4], ev[4];
        float vf[4];
#pragma unroll
        for (int k = 0; k < 4; k++) {
            const int jj = s16 + j + k;
            const int s = srcs[2 * jj];
            xv[k] = *reinterpret_cast<const float2*>(x + (size_t)s * DIM + c0);
            ev[k] = *reinterpret_cast<const float2*>(eb + (j + k) * 68 + c0);
            vf[k] = (jj < mK) ? 1.f : 0.f;
        }
#pragma unroll
        for (int k = 0; k < 4; k++) {
            acc0 = fmaf(vf[k], fmaxf(xv[k].x + ev[k].x + be0, 0.f), acc0);
            acc1 = fmaf(vf[k], fmaxf(xv[k].y + ev[k].y + be1, 0.f), acc1);
        }
    }
    __syncwarp();
}

__global__ void __launch_bounds__(128) aggregate_kernel(
    const float* __restrict__ x,
    const float* __restrict__ ea,       // [E, 16]
    const float* __restrict__ We,       // [16, 64]
    int N)
{
    extern __shared__ float dyn[];
    // carve: sbuf [4 warps][4 stages][640f] | ebuf [4 warps][1088f] | sd [4][4][32] int2
    float* sbuf = dyn;                                   // 10240 floats
    float* ebuf = dyn + 16 * SB_STAGE_F;                 // 4 * 1088 floats
    int2*  sd   = reinterpret_cast<int2*>(dyn + 16 * SB_STAGE_F + 4 * 1088);

    const int tid = threadIdx.x;
    const int lane = tid & 31;
    const int wrp  = tid >> 5;
    const int c0 = lane * 2;
    const int gID = lane >> 2, l4 = lane & 3;
    const int w = (blockIdx.x * blockDim.x + tid) >> 5;
    const int n0 = 4 * w;
    if (n0 >= N) return;

    // B fragments from We (cached in L1/L2; verified mapping)
    unsigned bf[8][2][2];
#pragma unroll
    for (int t = 0; t < 8; t++)
#pragma unroll
        for (int kk = 0; kk < 2; kk++) {
            bf[t][kk][0] = cvt_tf32(We[(kk * 8 + l4) * 64 + t * 8 + gID]);
            bf[t][kk][1] = cvt_tf32(We[(kk * 8 + l4 + 4) * 64 + t * 8 + gID]);
        }
    float be0, be1;
    upk2(be0, be1, g_bepack[lane]);

    const char* ea_bytes = reinterpret_cast<const char*>(ea);
    const int sub = lane >> 2;
    const int pc  = lane & 3;
    float* myeb = ebuf + wrp * 1088;

    int  deg[4];
    int2 er[4];
#pragma unroll
    for (int k = 0; k < 4; k++) {
        const int n = n0 + k;
        deg[k] = (n < N) ? min(g_cnt[n], CAP) : 0;
        er[k] = make_int2(0, 0);
        if (lane < deg[k]) er[k] = g_edges[(size_t)n * CAP + lane];
    }

    // stage records + commit all 4 ea chunks (80B padded rows)
#pragma unroll
    for (int k = 0; k < 4; k++) {
        sd[(wrp * 4 + k) * 32 + lane] = er[k];
        const int mK = min(32, deg[k]);
        const unsigned sbK = smem_u32(sbuf + (wrp * 4 + k) * SB_STAGE_F);
#pragma unroll
        for (int q = 0; q < 4; q++) {
            const int eidx = q * 8 + sub;
            const int id = __shfl_sync(0xFFFFFFFFu, er[k].y, eidx);
            if (eidx < mK)
                cpa16(sbK + (unsigned)(eidx * 80 + pc * 16),
                      ea_bytes + (size_t)id * 64 + pc * 16);
        }
        CP_COMMIT();
    }

#define PROCESS_NODE(K)                                                          \
    {                                                                            \
        __syncwarp();                                                            \
        const int n = n0 + K;                                                    \
        if (n < N) {                                                             \
            float acc0 = 0.f, acc1 = 0.f;                                        \
            const int dK = deg[K];                                               \
            const int mK = min(32, dK);                                          \
            const float* seK = sbuf + (wrp * 4 + K) * SB_STAGE_F;                \
            const int* srcsK = &sd[(wrp * 4 + K) * 32].x;                        \
            if (mK > 0)                                                          \
                mma16_epi(seK, myeb, srcsK, 0, mK, x, c0, gID, l4,               \
                          bf, be0, be1, acc0, acc1);                             \
            if (mK > 16)                                                         \
                mma16_epi(seK, myeb, srcsK, 16, mK, x, c0, gID, l4,              \
                          bf, be0, be1, acc0, acc1);                             \
            /* rare tail chunks (deg > 32) */                                    \
            for (int base = 32; base < dK; base += 32) {                         \
                __syncwarp();                                                    \
                const int m = min(32, dK - base);                                \
                int2 e2 = make_int2(0, 0);                                       \
                if (base + lane < dK) e2 = g_edges[(size_t)n * CAP + base + lane]; \
                sd[(wrp * 4 + K) * 32 + lane] = e2;                              \
                const unsigned sbK = smem_u32(sbuf + (wrp * 4 + K) * SB_STAGE_F);\
                for (int q = 0; q < 4; q++) {                                    \
                    const int eidx = q * 8 + sub;                                \
                    const int id = __shfl_sync(0xFFFFFFFFu, e2.y, eidx);         \
                    if (eidx < m)                                                \
                        cpa16(sbK + (unsigned)(eidx * 80 + pc * 16),             \
                              ea_bytes + (size_t)id * 64 + pc * 16);             \
                }                                                                \
                CP_COMMIT();                                                     \
                CP_WAIT(0);                                                      \
                __syncwarp();                                                    \
                mma16_epi(seK, myeb, srcsK, 0, m, x, c0, gID, l4,                \
                          bf, be0, be1, acc0, acc1);                             \
                if (m > 16)                                                      \
                    mma16_epi(seK, myeb, srcsK, 16, m, x, c0, gID, l4,           \
                              bf, be0, be1, acc0, acc1);                         \
            }                                                                    \
            const float2 xn = *reinterpret_cast<const float2*>(                  \
                x + (size_t)n * DIM + c0);                                       \
            *reinterpret_cast<float2*>(g_h + (size_t)n * DIM + c0) =             \
                make_float2(xn.x + acc0, xn.y + acc1);                           \
        }                                                                        \
    }

    CP_WAIT(3); PROCESS_NODE(0)
    CP_WAIT(2); PROCESS_NODE(1)
    CP_WAIT(1); PROCESS_NODE(2)
    CP_WAIT(0); PROCESS_NODE(3)
#undef PROCESS_NODE
}

#define AGG_SMEM_BYTES ((16 * SB_STAGE_F + 4 * 1088) * 4 + 4 * 4 * 32 * 8)

// ---------------------------------------------------------------------------
// k5: MLP via tf32 MMA (R15, proven ~12us)
// ---------------------------------------------------------------------------
#define HS2_LD 68
#define MLP2_SMEM ((128 * HS2_LD + 64 * 64 + 128) * 4)

__global__ void __launch_bounds__(256) mlp_mma_kernel(
    const float* __restrict__ W1, const float* __restrict__ b1,
    const float* __restrict__ W2, const float* __restrict__ b2,
    float* __restrict__ out, int N)
{
    extern __shared__ float smem[];
    float* hs  = smem;
    float* ws  = smem + 128 * HS2_LD;
    float* sb1 = ws + 64 * 64;
    float* sb2 = sb1 + 64;

    const int tid = threadIdx.x;
    const int nb = blockIdx.x * 128;

#pragma unroll
    for (int f = tid; f < 128 * 16; f += 256) {
        const int i = f >> 4, c4 = f & 15;
        float4 v = make_float4(0.f, 0.f, 0.f, 0.f);
        if (nb + i < N) v = reinterpret_cast<const float4*>(g_h)[(size_t)(nb + i) * 16 + c4];
        *reinterpret_cast<float4*>(hs + i * HS2_LD + c4 * 4) = v;
    }
    for (int f = tid; f < 1024; f += 256)
        *reinterpret_cast<float4*>(ws + f * 4) = reinterpret_cast<const float4*>(W1)[f];
    if (tid < 64) sb1[tid] = b1[tid];
    else if (tid < 128) sb2[tid - 64] = b2[tid - 64];
    __syncthreads();

    const int wrp = tid >> 5, lane = tid & 31;
    const int gID = lane >> 2, l4 = lane & 3;
    const int r0 = wrp * 16;

    float c[8][4];
#pragma unroll
    for (int t = 0; t < 8; t++) {
        const float2 bb = *reinterpret_cast<const float2*>(&sb1[t * 8 + 2 * l4]);
        c[t][0] = bb.x; c[t][1] = bb.y; c[t][2] = bb.x; c[t][3] = bb.y;
    }
#pragma unroll
    for (int kk = 0; kk < 8; kk++) {
        unsigned a[4];
        const float* h0 = hs + (r0 + gID) * HS2_LD + kk * 8;
        const float* h8 = hs + (r0 + gID + 8) * HS2_LD + kk * 8;
        a[0] = cvt_tf32(h0[l4]);     a[1] = cvt_tf32(h8[l4]);
        a[2] = cvt_tf32(h0[l4 + 4]); a[3] = cvt_tf32(h8[l4 + 4]);
#pragma unroll
        for (int t = 0; t < 8; t++) {
            unsigned b[2];
            b[0] = cvt_tf32(ws[(kk * 8 + l4) * 64 + t * 8 + gID]);
            b[1] = cvt_tf32(ws[(kk * 8 + l4 + 4) * 64 + t * 8 + gID]);
            mma_tf32(c[t], a, b);
        }
    }
    __syncthreads();

    for (int f = tid; f < 1024; f += 256)
        *reinterpret_cast<float4*>(ws + f * 4) = reinterpret_cast<const float4*>(W2)[f];
#pragma unroll
    for (int t = 0; t < 8; t++) {
        *reinterpret_cast<float2*>(hs + (r0 + gID) * HS2_LD + t * 8 + 2 * l4) =
            make_float2(fmaxf(c[t][0], 0.f), fmaxf(c[t][1], 0.f));
        *reinterpret_cast<float2*>(hs + (r0 + gID + 8) * HS2_LD + t * 8 + 2 * l4) =
            make_float2(fmaxf(c[t][2], 0.f), fmaxf(c[t][3], 0.f));
    }
    __syncthreads();

    float d[8][4];
#pragma unroll
    for (int t = 0; t < 8; t++) {
        const float2 bb = *reinterpret_cast<const float2*>(&sb2[t * 8 + 2 * l4]);
        d[t][0] = bb.x; d[t][1] = bb.y; d[t][2] = bb.x; d[t][3] = bb.y;
    }
#pragma unroll
    for (int kk = 0; kk < 8; kk++) {
        unsigned a[4];
        const float* h0 = hs + (r0 + gID) * HS2_LD + kk * 8;
        const float* h8 = hs + (r0 + gID + 8) * HS2_LD + kk * 8;
        a[0] = cvt_tf32(h0[l4]);     a[1] = cvt_tf32(h8[l4]);
        a[2] = cvt_tf32(h0[l4 + 4]); a[3] = cvt_tf32(h8[l4 + 4]);
#pragma unroll
        for (int t = 0; t < 8; t++) {
            unsigned b[2];
            b[0] = cvt_tf32(ws[(kk * 8 + l4) * 64 + t * 8 + gID]);
            b[1] = cvt_tf32(ws[(kk * 8 + l4 + 4) * 64 + t * 8 + gID]);
            mma_tf32(d[t], a, b);
        }
    }

    const int n0g = nb + r0 + gID;
    const int n8g = nb + r0 + gID + 8;
#pragma unroll
    for (int t = 0; t < 8; t++) {
        if (n0g < N)
            *reinterpret_cast<float2*>(out + (size_t)n0g * DIM + t * 8 + 2 * l4) =
                make_float2(d[t][0], d[t][1]);
        if (n8g < N)
            *reinterpret_cast<float2*>(out + (size_t)n8g * DIM + t * 8 + 2 * l4) =
                make_float2(d[t][2], d[t][3]);
    }
}

// ---------------------------------------------------------------------------
extern "C" void kernel_launch(void* const* d_in, const int* in_sizes, int n_in,
                              void* d_out, int out_size)
{
    const float* x  = (const float*)d_in[0];
    const int*   ei = (const int*)d_in[1];        // int32 (JAX x64 disabled)
    const float* ea = (const float*)d_in[2];
    const float* We = (const float*)d_in[3];
    const float* be = (const float*)d_in[4];
    const float* W1 = (const float*)d_in[5];
    const float* b1 = (const float*)d_in[6];
    const float* W2 = (const float*)d_in[7];
    const float* b2 = (const float*)d_in[8];
    float* out = (float*)d_out;

    const int N = in_sizes[0] / DIM;       // 100000
    const int E = in_sizes[1] / 2;         // 1600000

    void* cnt_ptr = nullptr;
    cudaGetSymbolAddress(&cnt_ptr, g_cnt);
    cudaMemsetAsync(cnt_ptr, 0, (size_t)N * sizeof(int));

    pack_we_kernel<<<2, 256>>>(We);                         // launch 1 (spacer)
    scatter_kernel<<<(E + 255) / 256, 256>>>(ei, E);        // launch 2
    pack_be_kernel<<<1, 32>>>(be);                          // launch 3

    const int quads = (N + 3) / 4;                          // one warp per 4 nodes
    cudaFuncSetAttribute(aggregate_kernel,
                         cudaFuncAttributeMaxDynamicSharedMemorySize, AGG_SMEM_BYTES);
    aggregate_kernel<<<(quads * 32 + 127) / 128, 128, AGG_SMEM_BYTES>>>(
        x, ea, We, N);                                      // launch 4 (profiled)

    cudaFuncSetAttribute(mlp_mma_kernel, cudaFuncAttributeMaxDynamicSharedMemorySize, MLP2_SMEM);
    mlp_mma_kernel<<<(N + 127) / 128, 256, MLP2_SMEM>>>(W1, b1, W2, b2, out, N);  // launch 5
}

// round 17
// speedup vs baseline: 1.0787x; 1.0787x over previous
#include <cuda_runtime.h>

#define DIM 64
#define MAX_NODES 100000
#define MAX_EDGES 1600000
#define CAP 64                       // fixed bucket capacity per node

typedef unsigned long long ull;

// ---- device scratch (no allocs allowed) ----
__device__ __align__(16) float g_h[MAX_NODES * DIM];      // h = x + aggr (written whole)
__device__ __align__(8) int2 g_edges[MAX_NODES * CAP];    // (src, edge_id) per dst bucket
__device__ int  g_cnt[MAX_NODES];

__device__ __forceinline__ ull pk2(float lo, float hi) {
    ull r; asm("mov.b64 %0, {%1, %2};" : "=l"(r) : "f"(lo), "f"(hi)); return r;
}
__device__ __forceinline__ void upk2(float& lo, float& hi, ull v) {
    asm("mov.b64 {%0, %1}, %2;" : "=f"(lo), "=f"(hi) : "l"(v));
}
__device__ __forceinline__ void ffma2(ull& d, ull a, ull b) {
    asm("fma.rn.f32x2 %0, %1, %2, %0;" : "+l"(d) : "l"(a), "l"(b));
}
__device__ __forceinline__ unsigned smem_u32(const void* p) {
    unsigned a;
    asm("{ .reg .u64 t; cvta.to.shared.u64 t, %1; cvt.u32.u64 %0, t; }"
        : "=r"(a) : "l"(p));
    return a;
}
__device__ __forceinline__ void cpa16(unsigned s, const void* g) {
    asm volatile("cp.async.ca.shared.global [%0], [%1], 16;" :: "r"(s), "l"(g));
}
#define CP_COMMIT()  asm volatile("cp.async.commit_group;")
#define CP_WAIT(kk)  asm volatile("cp.async.wait_group " #kk ";")

__device__ __forceinline__ unsigned cvt_tf32(float f) {
    unsigned r;
    asm("cvt.rna.tf32.f32 %0, %1;" : "=r"(r) : "f"(f));
    return r;
}
__device__ __forceinline__ void mma_tf32(float c[4], const unsigned a[4], const unsigned b[2]) {
    asm volatile(
        "mma.sync.aligned.m16n8k8.row.col.f32.tf32.tf32.f32 "
        "{%0,%1,%2,%3}, {%4,%5,%6,%7}, {%8,%9}, {%0,%1,%2,%3};"
        : "+f"(c[0]), "+f"(c[1]), "+f"(c[2]), "+f"(c[3])
        : "r"(a[0]), "r"(a[1]), "r"(a[2]), "r"(a[3]), "r"(b[0]), "r"(b[1]));
}

// ---------------------------------------------------------------------------
// k1: scatter (src, edge_id) into fixed-capacity dst buckets — 2 edges/thread
// ---------------------------------------------------------------------------
__global__ void scatter_kernel(const int* __restrict__ ei, int E) {
    const int e = (blockIdx.x * blockDim.x + threadIdx.x) * 2;
    if (e + 1 < E) {
        const int2 s2 = *reinterpret_cast<const int2*>(ei + e);
        const int2 d2 = *reinterpret_cast<const int2*>(ei + E + e);
        const int p0 = atomicAdd(&g_cnt[d2.x], 1);
        if (p0 < CAP) g_edges[(size_t)d2.x * CAP + p0] = make_int2(s2.x, e);
        const int p1 = atomicAdd(&g_cnt[d2.y], 1);
        if (p1 < CAP) g_edges[(size_t)d2.y * CAP + p1] = make_int2(s2.y, e + 1);
    } else if (e < E) {
        const int src = ei[e];
        const int dst = ei[E + e];
        const int p = atomicAdd(&g_cnt[dst], 1);
        if (p < CAP) g_edges[(size_t)dst * CAP + p] = make_int2(src, e);
    }
}

// ---------------------------------------------------------------------------
// k2: per-node aggregation, DEPTH-4 node pipeline (R12 core, proven 145us).
// We/be read directly (L2-hit LDG at warp startup; no pack kernels).
// ---------------------------------------------------------------------------
__device__ __forceinline__ void compute_chunk(
    const ulonglong2* su, const int* srcs, int m,
    const float* __restrict__ x, int c0,
    const ull* wA, const ull* wB, float be0, float be1,
    float& acc0, float& acc1)
{
    float2 xv[4];
#pragma unroll
    for (int k = 0; k < 4; k++) {
        const int s = srcs[2 * k];
        xv[k] = *reinterpret_cast<const float2*>(x + (size_t)s * DIM + c0);
    }
    for (int j = 0; j < m; j += 4) {
        float2 xvN[4];
        if (j + 4 < m) {
#pragma unroll
            for (int k = 0; k < 4; k++) {
                const int s = srcs[2 * (j + 4 + k)];
                xvN[k] = *reinterpret_cast<const float2*>(x + (size_t)s * DIM + c0);
            }
        }
        ull A[4], B[4];
#pragma unroll
        for (int k = 0; k < 4; k++) { A[k] = 0ull; B[k] = 0ull; }
#pragma unroll
        for (int k2p = 0; k2p < 4; k2p++) {
#pragma unroll
            for (int k = 0; k < 4; k++) {
                const ulonglong2 u = su[(j + k) * 4 + k2p];   // broadcast LDS.128
                ffma2(A[k], u.x, wA[2 * k2p]);
                ffma2(B[k], u.x, wB[2 * k2p]);
                ffma2(A[k], u.y, wA[2 * k2p + 1]);
                ffma2(B[k], u.y, wB[2 * k2p + 1]);
            }
        }
#pragma unroll
        for (int k = 0; k < 4; k++) {
            const float vf = (j + k < m) ? 1.f : 0.f;
            float lo0, hi0, lo1, hi1;
            upk2(lo0, hi0, A[k]);
            upk2(lo1, hi1, B[k]);
            acc0 = fmaf(vf, fmaxf(xv[k].x + (lo0 + hi0 + be0), 0.f), acc0);
            acc1 = fmaf(vf, fmaxf(xv[k].y + (lo1 + hi1 + be1), 0.f), acc1);
        }
#pragma unroll
        for (int k = 0; k < 4; k++) xv[k] = xvN[k];
    }
}

__global__ void __launch_bounds__(128) aggregate_kernel(
    const float* __restrict__ x,
    const float* __restrict__ ea,       // [E, 16]
    const float* __restrict__ We,       // [16, 64]
    const float* __restrict__ be,       // [64]
    int N)
{
    __shared__ __align__(16) float4 sbuf[4][4][128];  // warp, stage, 2KB ea chunk
    __shared__ int2 s_sd[4][4][32];                   // warp, stage, records

    const int tid = threadIdx.x;
    const int lane = tid & 31;
    const int wrp  = tid >> 5;
    const int c0 = lane * 2;
    const int w = (blockIdx.x * blockDim.x + tid) >> 5;
    const int n0 = 4 * w;
    if (n0 >= N) return;

    // pack We K-pairs in-register (L2-hit LDG, amortized over 4 nodes)
    ull wA[8], wB[8];
#pragma unroll
    for (int k2 = 0; k2 < 8; k2++) {
        const float2 r0 = *reinterpret_cast<const float2*>(We + (2 * k2) * DIM + c0);
        const float2 r1 = *reinterpret_cast<const float2*>(We + (2 * k2 + 1) * DIM + c0);
        wA[k2] = pk2(r0.x, r1.x);
        wB[k2] = pk2(r0.y, r1.y);
    }
    const float2 bev = *reinterpret_cast<const float2*>(be + c0);
    const float be0 = bev.x, be1 = bev.y;

    const char* ea_bytes = reinterpret_cast<const char*>(ea);
    const int sub = lane >> 2;
    const int pc  = lane & 3;

    int  deg[4];
    int2 er[4];
#pragma unroll
    for (int k = 0; k < 4; k++) {
        const int n = n0 + k;
        deg[k] = (n < N) ? min(g_cnt[n], CAP) : 0;
        er[k] = make_int2(0, 0);
        if (lane < deg[k]) er[k] = g_edges[(size_t)n * CAP + lane];
    }

#pragma unroll
    for (int k = 0; k < 4; k++) {
        s_sd[wrp][k][lane] = er[k];
        const int mK = min(32, deg[k]);
        const unsigned sbK = smem_u32(&sbuf[wrp][k][0]);
#pragma unroll
        for (int q = 0; q < 4; q++) {
            const int eidx = q * 8 + sub;
            const int id = __shfl_sync(0xFFFFFFFFu, er[k].y, eidx);
            if (eidx < mK)
                cpa16(sbK + (unsigned)(eidx * 64 + pc * 16),
                      ea_bytes + (size_t)id * 64 + pc * 16);
        }
        CP_COMMIT();
    }

#define PROCESS_NODE(K)                                                          \
    {                                                                            \
        __syncwarp();                                                            \
        const int n = n0 + K;                                                    \
        if (n < N) {                                                             \
            float acc0 = 0.f, acc1 = 0.f;                                        \
            const int dK = deg[K];                                               \
            const int mK = min(32, dK);                                          \
            if (mK > 0)                                                          \
                compute_chunk(reinterpret_cast<const ulonglong2*>(&sbuf[wrp][K][0]), \
                              &s_sd[wrp][K][0].x, mK, x, c0, wA, wB, be0, be1,   \
                              acc0, acc1);                                       \
            for (int base = 32; base < dK; base += 32) {                         \
                __syncwarp();                                                    \
                const int m = min(32, dK - base);                                \
                int2 e2 = make_int2(0, 0);                                       \
                if (base + lane < dK) e2 = g_edges[(size_t)n * CAP + base + lane]; \
                s_sd[wrp][K][lane] = e2;                                         \
                const unsigned sbK = smem_u32(&sbuf[wrp][K][0]);                 \
                for (int q = 0; q < 4; q++) {                                    \
                    const int eidx = q * 8 + sub;                                \
                    const int id = __shfl_sync(0xFFFFFFFFu, e2.y, eidx);         \
                    if (eidx < m)                                                \
                        cpa16(sbK + (unsigned)(eidx * 64 + pc * 16),             \
                              ea_bytes + (size_t)id * 64 + pc * 16);             \
                }                                                                \
                CP_COMMIT();                                                     \
                CP_WAIT(0);                                                      \
                __syncwarp();                                                    \
                compute_chunk(reinterpret_cast<const ulonglong2*>(&sbuf[wrp][K][0]), \
                              &s_sd[wrp][K][0].x, m, x, c0, wA, wB, be0, be1,    \
                              acc0, acc1);                                       \
            }                                                                    \
            const float2 xn = *reinterpret_cast<const float2*>(                  \
                x + (size_t)n * DIM + c0);                                       \
            *reinterpret_cast<float2*>(g_h + (size_t)n * DIM + c0) =             \
                make_float2(xn.x + acc0, xn.y + acc1);                           \
        }                                                                        \
    }

    CP_WAIT(3); PROCESS_NODE(0)
    CP_WAIT(2); PROCESS_NODE(1)
    CP_WAIT(1); PROCESS_NODE(2)
    CP_WAIT(0); PROCESS_NODE(3)
#undef PROCESS_NODE
}

// ---------------------------------------------------------------------------
// k3: MLP via tf32 MMA (R15, proven ~12us)
// ---------------------------------------------------------------------------
#define HS2_LD 68
#define MLP2_SMEM ((128 * HS2_LD + 64 * 64 + 128) * 4)

__global__ void __launch_bounds__(256) mlp_mma_kernel(
    const float* __restrict__ W1, const float* __restrict__ b1,
    const float* __restrict__ W2, const float* __restrict__ b2,
    float* __restrict__ out, int N)
{
    extern __shared__ float smem[];
    float* hs  = smem;
    float* ws  = smem + 128 * HS2_LD;
    float* sb1 = ws + 64 * 64;
    float* sb2 = sb1 + 64;

    const int tid = threadIdx.x;
    const int nb = blockIdx.x * 128;

#pragma unroll
    for (int f = tid; f < 128 * 16; f += 256) {
        const int i = f >> 4, c4 = f & 15;
        float4 v = make_float4(0.f, 0.f, 0.f, 0.f);
        if (nb + i < N) v = reinterpret_cast<const float4*>(g_h)[(size_t)(nb + i) * 16 + c4];
        *reinterpret_cast<float4*>(hs + i * HS2_LD + c4 * 4) = v;
    }
    for (int f = tid; f < 1024; f += 256)
        *reinterpret_cast<float4*>(ws + f * 4) = reinterpret_cast<const float4*>(W1)[f];
    if (tid < 64) sb1[tid] = b1[tid];
    else if (tid < 128) sb2[tid - 64] = b2[tid - 64];
    __syncthreads();

    const int wrp = tid >> 5, lane = tid & 31;
    const int gID = lane >> 2, l4 = lane & 3;
    const int r0 = wrp * 16;

    float c[8][4];
#pragma unroll
    for (int t = 0; t < 8; t++) {
        const float2 bb = *reinterpret_cast<const float2*>(&sb1[t * 8 + 2 * l4]);
        c[t][0] = bb.x; c[t][1] = bb.y; c[t][2] = bb.x; c[t][3] = bb.y;
    }
#pragma unroll
    for (int kk = 0; kk < 8; kk++) {
        unsigned a[4];
        const float* h0 = hs + (r0 + gID) * HS2_LD + kk * 8;
        const float* h8 = hs + (r0 + gID + 8) * HS2_LD + kk * 8;
        a[0] = cvt_tf32(h0[l4]);     a[1] = cvt_tf32(h8[l4]);
        a[2] = cvt_tf32(h0[l4 + 4]); a[3] = cvt_tf32(h8[l4 + 4]);
#pragma unroll
        for (int t = 0; t < 8; t++) {
            unsigned b[2];
            b[0] = cvt_tf32(ws[(kk * 8 + l4) * 64 + t * 8 + gID]);
            b[1] = cvt_tf32(ws[(kk * 8 + l4 + 4) * 64 + t * 8 + gID]);
            mma_tf32(c[t], a, b);
        }
    }
    __syncthreads();

    for (int f = tid; f < 1024; f += 256)
        *reinterpret_cast<float4*>(ws + f * 4) = reinterpret_cast<const float4*>(W2)[f];
#pragma unroll
    for (int t = 0; t < 8; t++) {
        *reinterpret_cast<float2*>(hs + (r0 + gID) * HS2_LD + t * 8 + 2 * l4) =
            make_float2(fmaxf(c[t][0], 0.f), fmaxf(c[t][1], 0.f));
        *reinterpret_cast<float2*>(hs + (r0 + gID + 8) * HS2_LD + t * 8 + 2 * l4) =
            make_float2(fmaxf(c[t][2], 0.f), fmaxf(c[t][3], 0.f));
    }
    __syncthreads();

    float d[8][4];
#pragma unroll
    for (int t = 0; t < 8; t++) {
        const float2 bb = *reinterpret_cast<const float2*>(&sb2[t * 8 + 2 * l4]);
        d[t][0] = bb.x; d[t][1] = bb.y; d[t][2] = bb.x; d[t][3] = bb.y;
    }
#pragma unroll
    for (int kk = 0; kk < 8; kk++) {
        unsigned a[4];
        const float* h0 = hs + (r0 + gID) * HS2_LD + kk * 8;
        const float* h8 = hs + (r0 + gID + 8) * HS2_LD + kk * 8;
        a[0] = cvt_tf32(h0[l4]);     a[1] = cvt_tf32(h8[l4]);
        a[2] = cvt_tf32(h0[l4 + 4]); a[3] = cvt_tf32(h8[l4 + 4]);
#pragma unroll
        for (int t = 0; t < 8; t++) {
            unsigned b[2];
            b[0] = cvt_tf32(ws[(kk * 8 + l4) * 64 + t * 8 + gID]);
            b[1] = cvt_tf32(ws[(kk * 8 + l4 + 4) * 64 + t * 8 + gID]);
            mma_tf32(d[t], a, b);
        }
    }

    const int n0g = nb + r0 + gID;
    const int n8g = nb + r0 + gID + 8;
#pragma unroll
    for (int t = 0; t < 8; t++) {
        if (n0g < N)
            *reinterpret_cast<float2*>(out + (size_t)n0g * DIM + t * 8 + 2 * l4) =
                make_float2(d[t][0], d[t][1]);
        if (n8g < N)
            *reinterpret_cast<float2*>(out + (size_t)n8g * DIM + t * 8 + 2 * l4) =
                make_float2(d[t][2], d[t][3]);
    }
}

// ---------------------------------------------------------------------------
extern "C" void kernel_launch(void* const* d_in, const int* in_sizes, int n_in,
                              void* d_out, int out_size)
{
    const float* x  = (const float*)d_in[0];
    const int*   ei = (const int*)d_in[1];        // int32 (JAX x64 disabled)
    const float* ea = (const float*)d_in[2];
    const float* We = (const float*)d_in[3];
    const float* be = (const float*)d_in[4];
    const float* W1 = (const float*)d_in[5];
    const float* b1 = (const float*)d_in[6];
    const float* W2 = (const float*)d_in[7];
    const float* b2 = (const float*)d_in[8];
    float* out = (float*)d_out;

    const int N = in_sizes[0] / DIM;       // 100000
    const int E = in_sizes[1] / 2;         // 1600000

    void* cnt_ptr = nullptr;
    cudaGetSymbolAddress(&cnt_ptr, g_cnt);
    cudaMemsetAsync(cnt_ptr, 0, (size_t)N * sizeof(int));

    const int pairsE = (E + 1) / 2;
    scatter_kernel<<<(pairsE + 255) / 256, 256>>>(ei, E);

    const int quads = (N + 3) / 4;                          // one warp per 4 nodes
    aggregate_kernel<<<(quads * 32 + 127) / 128, 128>>>(x, ea, We, be, N);

    cudaFuncSetAttribute(mlp_mma_kernel, cudaFuncAttributeMaxDynamicSharedMemorySize, MLP2_SMEM);
    mlp_mma_kernel<<<(N + 127) / 128, 256, MLP2_SMEM>>>(W1, b1, W2, b2, out, N);
}